// round 15
// baseline (speedup 1.0000x reference)
#include <cuda_runtime.h>
#include <cstdint>
#include <cstdio>

// ----------------------------------------------------------------------------
// Real spherical harmonic transform -> real part (float32 out).
//   Re X[row,m] = sum_j E[row,j] * (s*cos(2pi m j/720)),  row = b*360+k
//   out[b,n,m]  = sum_k Re X[b,k,m] * W[m,n,k]
// R15: R14 warp-direct streaming contract with the OOB fix: Xt padded to
// chunk-aligned KPC=384 k (shared reads at k in [360,384) hit staged zeros).
// ----------------------------------------------------------------------------

#define NTH   360
#define NLAM  720
#define NM    361
#define NB    8
#define ROWS  (NB*NTH) // 2880
#define ROWS_P 2944    // padded to multiple of 128
#define KP    368
#define MP    384

#define X_ELEMS (NB*NTH*NLAM)       // 2,073,600
#define W_ELEMS (NM*NTH*NTH)        // 46,785,600
#define OUT_ELEMS (NB*NTH*NM)       // 1,039,680 float32

__device__ float g_C  [KP * MP];        // [j][m] = s*cos(2pi m j / 720)
__device__ float g_E  [ROWS_P * KP];    // [row][j] even fold (pad rows zero)
__device__ float g_Xre[MP * ROWS_P];    // [m][row]

// ---------------------------------------------------------------- build table
__global__ void k_build_B() {
    int l = blockIdx.x;          // 0..367
    int m = threadIdx.x;         // 0..383
    float vc = 0.f;
    if (l <= 360) {
        int p = (l * m) % 720;
        float c = cospif((float)p * (1.0f / 360.0f));
        vc = 0.008726646259971648f * c;      // 2*pi/720
    }
    g_C[l * MP + m] = vc;
}

// ---------------------------------------------------------------- fold E
__global__ void k_fold(const float* __restrict__ x) {
    int idx = blockIdx.x * blockDim.x + threadIdx.x;
    if (idx >= ROWS_P * KP) return;
    int r = idx / KP;
    int j = idx - r * KP;
    float e = 0.f;
    if (r < ROWS && j <= 360) {
        const float* xr = x + r * NLAM;
        if (j == 0)        e = xr[0];
        else if (j == 360) e = xr[360];
        else               e = xr[j] + xr[NLAM - j];
    }
    g_E[idx] = e;
}

// ---------------------------------------------------------------- GEMM1 (DFT)
// Xre[row,m] = sum_j E[row,j] * C[j,m].  BM=128, BN=64, BK=16, 256 threads.
#define EPAD 132
#define CPAD 68
__global__ void __launch_bounds__(256) k_gemm1() {
    __shared__ __align__(16) float sE[16 * EPAD];   // [kk][row(128)]
    __shared__ __align__(16) float sC[16 * CPAD];   // [kk][m(64)]

    const int tid = threadIdx.x;
    const int ty  = tid >> 4;         // 0..15 -> rows ty*8 .. ty*8+7
    const int tx  = tid & 15;         // 0..15 -> m tx*4 .. tx*4+3
    const int m0   = blockIdx.x * 64;
    const int row0 = blockIdx.y * 128;

    float acc[8][4];
#pragma unroll
    for (int i = 0; i < 8; ++i)
#pragma unroll
        for (int j = 0; j < 4; ++j) acc[i][j] = 0.f;

    for (int k0 = 0; k0 < KP; k0 += 16) {
#pragma unroll
        for (int t = 0; t < 2; ++t) {
            int i = tid + t * 256;        // 0..511
            int r = i >> 2;               // 0..127
            int q = i & 3;
            float4 v = *reinterpret_cast<const float4*>(
                &g_E[(row0 + r) * KP + k0 + 4 * q]);
            sE[(4 * q + 0) * EPAD + r] = v.x;
            sE[(4 * q + 1) * EPAD + r] = v.y;
            sE[(4 * q + 2) * EPAD + r] = v.z;
            sE[(4 * q + 3) * EPAD + r] = v.w;
        }
        {
            int kk = tid >> 4;
            int q  = tid & 15;
            float4 v = *reinterpret_cast<const float4*>(
                &g_C[(k0 + kk) * MP + m0 + 4 * q]);
            *reinterpret_cast<float4*>(&sC[kk * CPAD + 4 * q]) = v;
        }
        __syncthreads();
#pragma unroll
        for (int kk = 0; kk < 16; ++kk) {
            float4 e0 = *reinterpret_cast<const float4*>(&sE[kk * EPAD + ty * 8]);
            float4 e1 = *reinterpret_cast<const float4*>(&sE[kk * EPAD + ty * 8 + 4]);
            float4 c  = *reinterpret_cast<const float4*>(&sC[kk * CPAD + tx * 4]);
            float e[8] = {e0.x, e0.y, e0.z, e0.w, e1.x, e1.y, e1.z, e1.w};
            float cv[4] = {c.x, c.y, c.z, c.w};
#pragma unroll
            for (int i = 0; i < 8; ++i)
#pragma unroll
                for (int j = 0; j < 4; ++j)
                    acc[i][j] = fmaf(e[i], cv[j], acc[i][j]);
        }
        __syncthreads();
    }
#pragma unroll
    for (int j = 0; j < 4; ++j) {
        int m = m0 + tx * 4 + j;
        float4 v0 = make_float4(acc[0][j], acc[1][j], acc[2][j], acc[3][j]);
        float4 v1 = make_float4(acc[4][j], acc[5][j], acc[6][j], acc[7][j]);
        *reinterpret_cast<float4*>(&g_Xre[m * ROWS_P + row0 + ty * 8])     = v0;
        *reinterpret_cast<float4*>(&g_Xre[m * ROWS_P + row0 + ty * 8 + 4]) = v1;
    }
}

// ---------------------------------------------------------------- contraction
// Grid (361, 15). Block = 128 threads = 4 warps; warp owns 6 n rows; block
// covers 24 n. Lanes own k (32 per chunk, 12 chunks, last predicated on W).
// No barriers in main loop; shfl butterfly reduces k over lanes.
#define CW   6                     // n rows per warp
#define CN   (4 * CW)              // 24 n per block
#define NYS  (NTH / CN)            // 15
#define NCH  12                    // ceil(360/32)
#define KPC  (NCH * 32)            // 384: chunk-aligned Xt k extent (OOB fix)

__global__ void __launch_bounds__(128) k_contract(const float* __restrict__ W,
                                                  float* __restrict__ out) {
    __shared__ __align__(16) float Xt[KPC * NB];   // [k][b], 12.3 KB, zero-pad

    const int m    = blockIdx.x;
    const int ys   = blockIdx.y;
    const int tid  = threadIdx.x;
    const int warp = tid >> 5;
    const int lane = tid & 31;

    // stage X transposed: Xt[k*8+b] = Xre[m][b*360+k]; k in [360,384) -> 0
    for (int i = tid; i < KPC * NB; i += 128) {
        int k = i >> 3;
        int b = i & 7;
        Xt[i] = (k < NTH) ? g_Xre[(size_t)m * ROWS_P + b * NTH + k] : 0.f;
    }
    __syncthreads();

    const int n0 = ys * CN + warp * CW;
    const float* Wn = W + (size_t)m * (NTH * NTH) + (size_t)n0 * NTH;

    float acc[CW][NB];
#pragma unroll
    for (int j = 0; j < CW; ++j)
#pragma unroll
        for (int b = 0; b < NB; ++b) acc[j][b] = 0.f;

#pragma unroll 4
    for (int c = 0; c < NCH; ++c) {
        const int k = 32 * c + lane;
        const bool ok = (k < NTH);
        float wv[CW];
#pragma unroll
        for (int j = 0; j < CW; ++j)
            wv[j] = ok ? __ldg(&Wn[(size_t)j * NTH + k]) : 0.f;   // coalesced rows
        float4 x0 = *reinterpret_cast<const float4*>(&Xt[k * 8]);      // in-bounds:
        float4 x1 = *reinterpret_cast<const float4*>(&Xt[k * 8 + 4]);  // k < KPC
        float xv[NB] = {x0.x, x0.y, x0.z, x0.w, x1.x, x1.y, x1.z, x1.w};
#pragma unroll
        for (int j = 0; j < CW; ++j)
#pragma unroll
            for (int b = 0; b < NB; ++b)
                acc[j][b] = fmaf(wv[j], xv[b], acc[j][b]);
    }

    // butterfly-reduce each accumulator over the 32 lanes
#pragma unroll
    for (int j = 0; j < CW; ++j)
#pragma unroll
        for (int b = 0; b < NB; ++b) {
            float v = acc[j][b];
            v += __shfl_xor_sync(0xFFFFFFFFu, v, 16);
            v += __shfl_xor_sync(0xFFFFFFFFu, v, 8);
            v += __shfl_xor_sync(0xFFFFFFFFu, v, 4);
            v += __shfl_xor_sync(0xFFFFFFFFu, v, 2);
            v += __shfl_xor_sync(0xFFFFFFFFu, v, 1);
            acc[j][b] = v;          // all lanes hold the sum
        }

    // scatter results; writer lane = (j*8+b) & 31 spreads the 48 STGs
#pragma unroll
    for (int j = 0; j < CW; ++j)
#pragma unroll
        for (int b = 0; b < NB; ++b)
            if (lane == ((j * NB + b) & 31))
                out[(size_t)(b * NTH + n0 + j) * NM + m] = acc[j][b];
}

// ---------------------------------------------------------------- host diag
static bool sync_check(const char* stage) {
    cudaError_t e = cudaDeviceSynchronize();
    if (e == cudaSuccess) e = cudaGetLastError();
    if (e != cudaSuccess) {
        fprintf(stderr, "[diag] stage %-10s : %s\n", stage, cudaGetErrorString(e));
        fflush(stderr);
        return false;
    }
    return true;
}

// ---------------------------------------------------------------- launch
extern "C" void kernel_launch(void* const* d_in, const int* in_sizes, int n_in,
                              void* d_out, int out_size) {
    const float* x = nullptr;
    const float* w = nullptr;
    for (int i = 0; i < n_in; ++i) {
        if (in_sizes[i] == X_ELEMS && !x) x = (const float*)d_in[i];
        else if (in_sizes[i] == W_ELEMS && !w) w = (const float*)d_in[i];
    }
    float* out = (float*)d_out;
    if (!x || !w) return;

    cudaStreamCaptureStatus st = cudaStreamCaptureStatusNone;
    cudaStreamIsCapturing((cudaStream_t)0, &st);
    const bool capturing = (st != cudaStreamCaptureStatusNone);

    if (!capturing) {
        k_build_B<<<KP, MP>>>();
        if (!sync_check("build_B")) return;
        k_fold<<<(ROWS_P * KP + 255) / 256, 256>>>(x);
        if (!sync_check("fold")) return;
        k_gemm1<<<dim3(MP / 64, ROWS_P / 128), 256>>>();
        if (!sync_check("gemm1")) return;
        k_contract<<<dim3(NM, NYS), 128>>>(w, out);
        if (!sync_check("contract")) return;
        return;
    }

    k_build_B<<<KP, MP>>>();
    k_fold<<<(ROWS_P * KP + 255) / 256, 256>>>(x);
    k_gemm1<<<dim3(MP / 64, ROWS_P / 128), 256>>>();
    k_contract<<<dim3(NM, NYS), 128>>>(w, out);
}

// round 16
// speedup vs baseline: 1.3542x; 1.3542x over previous
#include <cuda_runtime.h>
#include <cstdint>
#include <cstdio>

// ----------------------------------------------------------------------------
// Real spherical harmonic transform -> real part (float32 out).
//   Re X[row,m] = sum_j E[row,j] * (s*cos(2pi m j/720)),  row = b*360+k
//   out[b,n,m]  = sum_k Re X[b,k,m] * W[m,n,k]
// R16: contract = R10 architecture (reg-prefetch double-buffer, best measured)
// scaled to n-split 3 / 128-thread blocks for ~7 independent blocks per SM.
// ----------------------------------------------------------------------------

#define NTH   360
#define NLAM  720
#define NM    361
#define NB    8
#define ROWS  (NB*NTH) // 2880
#define ROWS_P 2944    // padded to multiple of 128
#define KP    368
#define MP    384

#define X_ELEMS (NB*NTH*NLAM)       // 2,073,600
#define W_ELEMS (NM*NTH*NTH)        // 46,785,600
#define OUT_ELEMS (NB*NTH*NM)       // 1,039,680 float32

__device__ float g_C  [KP * MP];        // [j][m] = s*cos(2pi m j / 720)
__device__ float g_E  [ROWS_P * KP];    // [row][j] even fold (pad rows zero)
__device__ float g_Xre[MP * ROWS_P];    // [m][row]

// ---------------------------------------------------------------- build table
__global__ void k_build_B() {
    int l = blockIdx.x;          // 0..367
    int m = threadIdx.x;         // 0..383
    float vc = 0.f;
    if (l <= 360) {
        int p = (l * m) % 720;
        float c = cospif((float)p * (1.0f / 360.0f));
        vc = 0.008726646259971648f * c;      // 2*pi/720
    }
    g_C[l * MP + m] = vc;
}

// ---------------------------------------------------------------- fold E
__global__ void k_fold(const float* __restrict__ x) {
    int idx = blockIdx.x * blockDim.x + threadIdx.x;
    if (idx >= ROWS_P * KP) return;
    int r = idx / KP;
    int j = idx - r * KP;
    float e = 0.f;
    if (r < ROWS && j <= 360) {
        const float* xr = x + r * NLAM;
        if (j == 0)        e = xr[0];
        else if (j == 360) e = xr[360];
        else               e = xr[j] + xr[NLAM - j];
    }
    g_E[idx] = e;
}

// ---------------------------------------------------------------- GEMM1 (DFT)
// Xre[row,m] = sum_j E[row,j] * C[j,m].  BM=128, BN=64, BK=16, 256 threads.
#define EPAD 132
#define CPAD 68
__global__ void __launch_bounds__(256) k_gemm1() {
    __shared__ __align__(16) float sE[16 * EPAD];   // [kk][row(128)]
    __shared__ __align__(16) float sC[16 * CPAD];   // [kk][m(64)]

    const int tid = threadIdx.x;
    const int ty  = tid >> 4;         // 0..15 -> rows ty*8 .. ty*8+7
    const int tx  = tid & 15;         // 0..15 -> m tx*4 .. tx*4+3
    const int m0   = blockIdx.x * 64;
    const int row0 = blockIdx.y * 128;

    float acc[8][4];
#pragma unroll
    for (int i = 0; i < 8; ++i)
#pragma unroll
        for (int j = 0; j < 4; ++j) acc[i][j] = 0.f;

    for (int k0 = 0; k0 < KP; k0 += 16) {
#pragma unroll
        for (int t = 0; t < 2; ++t) {
            int i = tid + t * 256;        // 0..511
            int r = i >> 2;               // 0..127
            int q = i & 3;
            float4 v = *reinterpret_cast<const float4*>(
                &g_E[(row0 + r) * KP + k0 + 4 * q]);
            sE[(4 * q + 0) * EPAD + r] = v.x;
            sE[(4 * q + 1) * EPAD + r] = v.y;
            sE[(4 * q + 2) * EPAD + r] = v.z;
            sE[(4 * q + 3) * EPAD + r] = v.w;
        }
        {
            int kk = tid >> 4;
            int q  = tid & 15;
            float4 v = *reinterpret_cast<const float4*>(
                &g_C[(k0 + kk) * MP + m0 + 4 * q]);
            *reinterpret_cast<float4*>(&sC[kk * CPAD + 4 * q]) = v;
        }
        __syncthreads();
#pragma unroll
        for (int kk = 0; kk < 16; ++kk) {
            float4 e0 = *reinterpret_cast<const float4*>(&sE[kk * EPAD + ty * 8]);
            float4 e1 = *reinterpret_cast<const float4*>(&sE[kk * EPAD + ty * 8 + 4]);
            float4 c  = *reinterpret_cast<const float4*>(&sC[kk * CPAD + tx * 4]);
            float e[8] = {e0.x, e0.y, e0.z, e0.w, e1.x, e1.y, e1.z, e1.w};
            float cv[4] = {c.x, c.y, c.z, c.w};
#pragma unroll
            for (int i = 0; i < 8; ++i)
#pragma unroll
                for (int j = 0; j < 4; ++j)
                    acc[i][j] = fmaf(e[i], cv[j], acc[i][j]);
        }
        __syncthreads();
    }
#pragma unroll
    for (int j = 0; j < 4; ++j) {
        int m = m0 + tx * 4 + j;
        float4 v0 = make_float4(acc[0][j], acc[1][j], acc[2][j], acc[3][j]);
        float4 v1 = make_float4(acc[4][j], acc[5][j], acc[6][j], acc[7][j]);
        *reinterpret_cast<float4*>(&g_Xre[m * ROWS_P + row0 + ty * 8])     = v0;
        *reinterpret_cast<float4*>(&g_Xre[m * ROWS_P + row0 + ty * 8 + 4]) = v1;
    }
}

// ---------------------------------------------------------------- contraction
// Grid (361, 3): (m, n-third). 128 threads, thread t owns n=t (<120), 8 b.
// Reg-prefetch double-buffered W stream (R10 architecture, best measured).
#define NSPL 3
#define NPB  (NTH / NSPL)          // 120
#define KC2  16
#define WST  20
#define NPH  ((NTH + KC2 - 1) / KC2)   // 23
#define PF4  (NPB * (KC2 / 4))         // 480 float4 slots per stage

__global__ void __launch_bounds__(128) k_contract(const float* __restrict__ W,
                                                  float* __restrict__ out) {
    __shared__ __align__(16) float Xs[ROWS + KC2];        // 11.6 KB
    __shared__ __align__(16) float Ws[2][NPB * WST];      // 2 x 9.6 KB

    const int m   = blockIdx.x;
    const int ys  = blockIdx.y;
    const int tid = threadIdx.x;
    const int n   = tid;
    const bool live = (n < NPB);

    const float* Wm = W + (size_t)m * (NTH * NTH) + (size_t)ys * NPB * NTH;

    for (int i = tid; i < ROWS + KC2; i += 128)
        Xs[i] = (i < ROWS) ? g_Xre[(size_t)m * ROWS_P + i] : 0.f;

    float4 pf[4];
    auto prefetch = [&](int k0) {
#pragma unroll
        for (int u = 0; u < 4; ++u) {
            int i = tid + 128 * u;            // 0..511, 480 used
            float4 v = make_float4(0.f, 0.f, 0.f, 0.f);
            if (i < PF4) {
                int nl = i >> 2;
                int k  = k0 + (i & 3) * 4;
                if (k < NTH)
                    v = *reinterpret_cast<const float4*>(Wm + (size_t)nl * NTH + k);
            }
            pf[u] = v;
        }
    };
    auto store_buf = [&](int buf) {
#pragma unroll
        for (int u = 0; u < 4; ++u) {
            int i = tid + 128 * u;
            if (i < PF4) {
                int nl = i >> 2;
                int kb = (i & 3) * 4;
                *reinterpret_cast<float4*>(&Ws[buf][nl * WST + kb]) = pf[u];
            }
        }
    };

    prefetch(0);
    store_buf(0);
    __syncthreads();

    float acc[8];
#pragma unroll
    for (int b = 0; b < 8; ++b) acc[b] = 0.f;

    for (int p = 0; p < NPH; ++p) {
        const int k0 = p * KC2;
        if (p + 1 < NPH) prefetch(k0 + KC2);      // LDGs overlap compute
        const int buf = p & 1;
        if (live) {
#pragma unroll
            for (int q = 0; q < KC2 / 4; ++q) {
                float4 wv = *reinterpret_cast<const float4*>(&Ws[buf][n * WST + 4 * q]);
#pragma unroll
                for (int b = 0; b < 8; ++b) {
                    float4 xv = *reinterpret_cast<const float4*>(
                        &Xs[b * NTH + k0 + 4 * q]);   // warp-broadcast
                    acc[b] = fmaf(xv.x, wv.x, acc[b]);
                    acc[b] = fmaf(xv.y, wv.y, acc[b]);
                    acc[b] = fmaf(xv.z, wv.z, acc[b]);
                    acc[b] = fmaf(xv.w, wv.w, acc[b]);
                }
            }
        }
        __syncthreads();
        if (p + 1 < NPH) {
            store_buf((p + 1) & 1);
            __syncthreads();
        }
    }

    if (live) {
        const int ng = ys * NPB + n;
#pragma unroll
        for (int b = 0; b < 8; ++b)
            out[(size_t)(b * NTH + ng) * NM + m] = acc[b];
    }
}

// ---------------------------------------------------------------- host diag
static bool sync_check(const char* stage) {
    cudaError_t e = cudaDeviceSynchronize();
    if (e == cudaSuccess) e = cudaGetLastError();
    if (e != cudaSuccess) {
        fprintf(stderr, "[diag] stage %-10s : %s\n", stage, cudaGetErrorString(e));
        fflush(stderr);
        return false;
    }
    return true;
}

// ---------------------------------------------------------------- launch
extern "C" void kernel_launch(void* const* d_in, const int* in_sizes, int n_in,
                              void* d_out, int out_size) {
    const float* x = nullptr;
    const float* w = nullptr;
    for (int i = 0; i < n_in; ++i) {
        if (in_sizes[i] == X_ELEMS && !x) x = (const float*)d_in[i];
        else if (in_sizes[i] == W_ELEMS && !w) w = (const float*)d_in[i];
    }
    float* out = (float*)d_out;
    if (!x || !w) return;

    cudaStreamCaptureStatus st = cudaStreamCaptureStatusNone;
    cudaStreamIsCapturing((cudaStream_t)0, &st);
    const bool capturing = (st != cudaStreamCaptureStatusNone);

    if (!capturing) {
        k_build_B<<<KP, MP>>>();
        if (!sync_check("build_B")) return;
        k_fold<<<(ROWS_P * KP + 255) / 256, 256>>>(x);
        if (!sync_check("fold")) return;
        k_gemm1<<<dim3(MP / 64, ROWS_P / 128), 256>>>();
        if (!sync_check("gemm1")) return;
        k_contract<<<dim3(NM, NSPL), 128>>>(w, out);
        if (!sync_check("contract")) return;
        return;
    }

    k_build_B<<<KP, MP>>>();
    k_fold<<<(ROWS_P * KP + 255) / 256, 256>>>(x);
    k_gemm1<<<dim3(MP / 64, ROWS_P / 128), 256>>>();
    k_contract<<<dim3(NM, NSPL), 128>>>(w, out);
}

// round 17
// speedup vs baseline: 1.4870x; 1.0980x over previous
#include <cuda_runtime.h>
#include <cstdint>
#include <cstdio>

// ----------------------------------------------------------------------------
// Real spherical harmonic transform -> real part (float32 out).
//   Re X[row,m] = sum_j E[row,j] * (s*cos(2pi m j/720)),  row = b*360+k
//   out[b,n,m]  = sum_k Re X[b,k,m] * W[m,n,k]
// R17: contract = R16 double-buffer + packed f32x2 k-pair accumulation,
// 2 n-rows per thread (owner-strided smem, conflict-free), SMSP parity spread.
// ----------------------------------------------------------------------------

#define NTH   360
#define NLAM  720
#define NM    361
#define NB    8
#define ROWS  (NB*NTH) // 2880
#define ROWS_P 2944
#define KP    368
#define MP    384

#define X_ELEMS (NB*NTH*NLAM)       // 2,073,600
#define W_ELEMS (NM*NTH*NTH)        // 46,785,600
#define OUT_ELEMS (NB*NTH*NM)       // 1,039,680 float32

__device__ float g_C  [KP * MP];
__device__ float g_E  [ROWS_P * KP];
__device__ float g_Xre[MP * ROWS_P];

typedef unsigned long long ull;
__device__ __forceinline__ ull f2fma(ull a, ull b, ull c) {
    ull d;
    asm("fma.rn.f32x2 %0, %1, %2, %3;" : "=l"(d) : "l"(a), "l"(b), "l"(c));
    return d;
}

// ---------------------------------------------------------------- build table
__global__ void k_build_B() {
    int l = blockIdx.x;
    int m = threadIdx.x;
    float vc = 0.f;
    if (l <= 360) {
        int p = (l * m) % 720;
        float c = cospif((float)p * (1.0f / 360.0f));
        vc = 0.008726646259971648f * c;
    }
    g_C[l * MP + m] = vc;
}

// ---------------------------------------------------------------- fold E
__global__ void k_fold(const float* __restrict__ x) {
    int idx = blockIdx.x * blockDim.x + threadIdx.x;
    if (idx >= ROWS_P * KP) return;
    int r = idx / KP;
    int j = idx - r * KP;
    float e = 0.f;
    if (r < ROWS && j <= 360) {
        const float* xr = x + r * NLAM;
        if (j == 0)        e = xr[0];
        else if (j == 360) e = xr[360];
        else               e = xr[j] + xr[NLAM - j];
    }
    g_E[idx] = e;
}

// ---------------------------------------------------------------- GEMM1 (DFT)
#define EPAD 132
#define CPAD 68
__global__ void __launch_bounds__(256) k_gemm1() {
    __shared__ __align__(16) float sE[16 * EPAD];
    __shared__ __align__(16) float sC[16 * CPAD];

    const int tid = threadIdx.x;
    const int ty  = tid >> 4;
    const int tx  = tid & 15;
    const int m0   = blockIdx.x * 64;
    const int row0 = blockIdx.y * 128;

    float acc[8][4];
#pragma unroll
    for (int i = 0; i < 8; ++i)
#pragma unroll
        for (int j = 0; j < 4; ++j) acc[i][j] = 0.f;

    for (int k0 = 0; k0 < KP; k0 += 16) {
#pragma unroll
        for (int t = 0; t < 2; ++t) {
            int i = tid + t * 256;
            int r = i >> 2;
            int q = i & 3;
            float4 v = *reinterpret_cast<const float4*>(
                &g_E[(row0 + r) * KP + k0 + 4 * q]);
            sE[(4 * q + 0) * EPAD + r] = v.x;
            sE[(4 * q + 1) * EPAD + r] = v.y;
            sE[(4 * q + 2) * EPAD + r] = v.z;
            sE[(4 * q + 3) * EPAD + r] = v.w;
        }
        {
            int kk = tid >> 4;
            int q  = tid & 15;
            float4 v = *reinterpret_cast<const float4*>(
                &g_C[(k0 + kk) * MP + m0 + 4 * q]);
            *reinterpret_cast<float4*>(&sC[kk * CPAD + 4 * q]) = v;
        }
        __syncthreads();
#pragma unroll
        for (int kk = 0; kk < 16; ++kk) {
            float4 e0 = *reinterpret_cast<const float4*>(&sE[kk * EPAD + ty * 8]);
            float4 e1 = *reinterpret_cast<const float4*>(&sE[kk * EPAD + ty * 8 + 4]);
            float4 c  = *reinterpret_cast<const float4*>(&sC[kk * CPAD + tx * 4]);
            float e[8] = {e0.x, e0.y, e0.z, e0.w, e1.x, e1.y, e1.z, e1.w};
            float cv[4] = {c.x, c.y, c.z, c.w};
#pragma unroll
            for (int i = 0; i < 8; ++i)
#pragma unroll
                for (int j = 0; j < 4; ++j)
                    acc[i][j] = fmaf(e[i], cv[j], acc[i][j]);
        }
        __syncthreads();
    }
#pragma unroll
    for (int j = 0; j < 4; ++j) {
        int m = m0 + tx * 4 + j;
        float4 v0 = make_float4(acc[0][j], acc[1][j], acc[2][j], acc[3][j]);
        float4 v1 = make_float4(acc[4][j], acc[5][j], acc[6][j], acc[7][j]);
        *reinterpret_cast<float4*>(&g_Xre[m * ROWS_P + row0 + ty * 8])     = v0;
        *reinterpret_cast<float4*>(&g_Xre[m * ROWS_P + row0 + ty * 8 + 4]) = v1;
    }
}

// ---------------------------------------------------------------- contraction
// Grid (361, 3). 128 threads. Two live warps per block (parity-selected so
// SMSP load alternates per block). Live thread owns 2 n rows and all 8 b,
// accumulating (k-even,k-odd) pairs in f32x2. Reg-prefetch double buffer.
#define NSPL 3
#define NPB  (NTH / NSPL)          // 120
#define KC2  16
#define OST  36                    // owner stride (2 rows x 16 floats + 4 pad)
#define NOWN (NPB / 2)             // 60 owners
#define NPH  ((NTH + KC2 - 1) / KC2)   // 23
#define PF4  (NPB * (KC2 / 4))         // 480 float4 slots per stage

__global__ void __launch_bounds__(128) k_contract(const float* __restrict__ W,
                                                  float* __restrict__ out) {
    __shared__ __align__(16) float Xs[ROWS + KC2];        // 11.6 KB
    __shared__ __align__(16) float Ws[2][NOWN * OST];     // 2 x 8.6 KB

    const int m    = blockIdx.x;
    const int ys   = blockIdx.y;
    const int tid  = threadIdx.x;
    const int warp = tid >> 5;
    const int lane = tid & 31;
    const int bpar = (int)(blockIdx.x & 1);

    // live warp pair: warps with (warp&1)==bpar -> SMSP {0,2} or {1,3}
    const bool wlive = ((warp & 1) == bpar);
    const int  o     = (warp >> 1) * 32 + lane;     // owner id 0..63
    const bool live  = wlive && (o < NOWN);

    const float* Wm = W + (size_t)m * (NTH * NTH) + (size_t)ys * NPB * NTH;

    for (int i = tid; i < ROWS + KC2; i += 128)
        Xs[i] = (i < ROWS) ? g_Xre[(size_t)m * ROWS_P + i] : 0.f;

    float4 pf[4];
    auto prefetch = [&](int k0) {
#pragma unroll
        for (int u = 0; u < 4; ++u) {
            int i = tid + 128 * u;            // 0..511, 480 used
            float4 v = make_float4(0.f, 0.f, 0.f, 0.f);
            if (i < PF4) {
                int nl = i >> 2;              // local n row 0..119
                int k  = k0 + (i & 3) * 4;
                if (k < NTH)
                    v = *reinterpret_cast<const float4*>(Wm + (size_t)nl * NTH + k);
            }
            pf[u] = v;
        }
    };
    auto store_buf = [&](int buf) {
#pragma unroll
        for (int u = 0; u < 4; ++u) {
            int i = tid + 128 * u;
            if (i < PF4) {
                int nl = i >> 2;
                int kb = (i & 3) * 4;
                float* dst = &Ws[buf][(nl >> 1) * OST + (nl & 1) * 16 + kb];
                *reinterpret_cast<float4*>(dst) = pf[u];
            }
        }
    };

    prefetch(0);
    store_buf(0);
    __syncthreads();

    ull acc[2][NB];                 // f32x2 accumulators (k-even, k-odd)
#pragma unroll
    for (int r = 0; r < 2; ++r)
#pragma unroll
        for (int b = 0; b < NB; ++b) acc[r][b] = 0ull;

    for (int p = 0; p < NPH; ++p) {
        const int k0 = p * KC2;
        if (p + 1 < NPH) prefetch(k0 + KC2);
        const float* Wb = Ws[p & 1];
        if (live) {
#pragma unroll
            for (int q = 0; q < KC2 / 4; ++q) {
                ulonglong2 wa = *reinterpret_cast<const ulonglong2*>(
                    &Wb[o * OST + 4 * q]);          // row 2o,   4 k
                ulonglong2 wb = *reinterpret_cast<const ulonglong2*>(
                    &Wb[o * OST + 16 + 4 * q]);     // row 2o+1, 4 k
#pragma unroll
                for (int b = 0; b < NB; ++b) {
                    ulonglong2 xv = *reinterpret_cast<const ulonglong2*>(
                        &Xs[b * NTH + k0 + 4 * q]); // broadcast, 4 k
                    acc[0][b] = f2fma(xv.x, wa.x, acc[0][b]);
                    acc[0][b] = f2fma(xv.y, wa.y, acc[0][b]);
                    acc[1][b] = f2fma(xv.x, wb.x, acc[1][b]);
                    acc[1][b] = f2fma(xv.y, wb.y, acc[1][b]);
                }
            }
        }
        __syncthreads();
        if (p + 1 < NPH) {
            store_buf((p + 1) & 1);
            __syncthreads();
        }
    }

    if (live) {
#pragma unroll
        for (int r = 0; r < 2; ++r) {
            const int ng = ys * NPB + 2 * o + r;
#pragma unroll
            for (int b = 0; b < NB; ++b) {
                float2 v = *reinterpret_cast<const float2*>(&acc[r][b]);
                out[(size_t)(b * NTH + ng) * NM + m] = v.x + v.y;
            }
        }
    }
}

// ---------------------------------------------------------------- host diag
static bool sync_check(const char* stage) {
    cudaError_t e = cudaDeviceSynchronize();
    if (e == cudaSuccess) e = cudaGetLastError();
    if (e != cudaSuccess) {
        fprintf(stderr, "[diag] stage %-10s : %s\n", stage, cudaGetErrorString(e));
        fflush(stderr);
        return false;
    }
    return true;
}

// ---------------------------------------------------------------- launch
extern "C" void kernel_launch(void* const* d_in, const int* in_sizes, int n_in,
                              void* d_out, int out_size) {
    const float* x = nullptr;
    const float* w = nullptr;
    for (int i = 0; i < n_in; ++i) {
        if (in_sizes[i] == X_ELEMS && !x) x = (const float*)d_in[i];
        else if (in_sizes[i] == W_ELEMS && !w) w = (const float*)d_in[i];
    }
    float* out = (float*)d_out;
    if (!x || !w) return;

    cudaStreamCaptureStatus st = cudaStreamCaptureStatusNone;
    cudaStreamIsCapturing((cudaStream_t)0, &st);
    const bool capturing = (st != cudaStreamCaptureStatusNone);

    if (!capturing) {
        k_build_B<<<KP, MP>>>();
        if (!sync_check("build_B")) return;
        k_fold<<<(ROWS_P * KP + 255) / 256, 256>>>(x);
        if (!sync_check("fold")) return;
        k_gemm1<<<dim3(MP / 64, ROWS_P / 128), 256>>>();
        if (!sync_check("gemm1")) return;
        k_contract<<<dim3(NM, NSPL), 128>>>(w, out);
        if (!sync_check("contract")) return;
        return;
    }

    k_build_B<<<KP, MP>>>();
    k_fold<<<(ROWS_P * KP + 255) / 256, 256>>>(x);
    k_gemm1<<<dim3(MP / 64, ROWS_P / 128), 256>>>();
    k_contract<<<dim3(NM, NSPL), 128>>>(w, out);
}